// round 5
// baseline (speedup 1.0000x reference)
#include <cuda_runtime.h>
#include <cstdint>

#define NB 4
#define NP 8192
#define ND 512
#define NS1 4096
#define NS2 2048
#define ROWS_PER_B (NP + NS1 + NS2)   /* 14336 */
#define OUTX_ELEMS ((size_t)NB * ROWS_PER_B * ND)
#define TPB 1024
#define NCOPY 144                      /* copy CTAs fused into fps launch */

/* smem layout (bytes) */
#define OFF_WCAND 0        /* uint2[64]  = 512           */
#define OFF_CNT   512      /* int ssum, int sxor         */
#define OFF_SX    1024
#define OFF_SY    (OFF_SX + NP * 4)
#define OFF_SZ    (OFF_SY + NP * 4)
#define OFF_KEY   (OFF_SZ + NP * 4)          /* u32[8192] */
#define OFF_SID   (OFF_KEY + NP * 4)         /* u16[8192] */
#define SMEM_TOTAL (OFF_SID + NP * 2)        /* 148480 B  */

__device__ int g_fps_idx[NB * NS1];

/* ---------------- packed f32x2 helpers (proven) -------------------- */
__device__ __forceinline__ unsigned long long f32x2_add(unsigned long long a, unsigned long long b) {
    unsigned long long r;
    asm("add.rn.f32x2 %0, %1, %2;" : "=l"(r) : "l"(a), "l"(b));
    return r;
}
__device__ __forceinline__ unsigned long long f32x2_mul(unsigned long long a, unsigned long long b) {
    unsigned long long r;
    asm("mul.rn.f32x2 %0, %1, %2;" : "=l"(r) : "l"(a), "l"(b));
    return r;
}
__device__ __forceinline__ unsigned long long pack2(float lo, float hi) {
    unsigned long long r;
    asm("mov.b64 %0, {%1, %2};" : "=l"(r) : "f"(lo), "f"(hi));
    return r;
}
__device__ __forceinline__ void unpack2(unsigned long long v, float& lo, float& hi) {
    asm("mov.b64 {%0, %1}, %2;" : "=f"(lo), "=f"(hi) : "l"(v));
}

/* ---------------- Morton helpers ----------------------------------- */
__device__ __forceinline__ unsigned expand10(unsigned v) {
    v &= 0x3FFu;
    v = (v | (v << 16)) & 0x030000FFu;
    v = (v | (v <<  8)) & 0x0300F00Fu;
    v = (v | (v <<  4)) & 0x030C30C3u;
    v = (v | (v <<  2)) & 0x09249249u;
    return v;
}
__device__ __forceinline__ unsigned quant10(float x) {
    float q = (x + 8.0f) * 64.0f;
    q = fminf(fmaxf(q, 0.0f), 1023.0f);
    return (unsigned)q;
}

/* ===================================================================
   Fused kernel.
   blockIdx < NB   : FPS for batch blockIdx (round-4 algorithm + a
                     warp-uniform AABB pre-test and cached warp
                     candidates; all skips provably exact).
   blockIdx >= NB  : static-copy CTAs — stream the scale-1.0 rows of
                     fused_x / fused_p (independent of FPS) on the
                     otherwise idle SMs, overlapped under FPS.
   =================================================================== */
__global__ void __launch_bounds__(TPB, 1) fps_kernel(const float* __restrict__ pos,
                                                     const float* __restrict__ x,
                                                     float* __restrict__ outx,
                                                     float* __restrict__ outp)
{
    /* ------------------- static copy path -------------------------- */
    if (blockIdx.x >= NB) {
        const int  ct  = (int)(blockIdx.x - NB) * TPB + threadIdx.x;   /* 0..147455 */
        const int  nth = NCOPY * TPB;
        const float4* x4 = reinterpret_cast<const float4*>(x);
        float4*       o4 = reinterpret_cast<float4*>(outx);
        /* fused_x rows b*ROWS+o <- x row b*NP+o, o<NP. src f4 idx == idx. */
        const int totf4 = NB * NP * (ND / 4);
        for (int idx = ct; idx < totf4; idx += nth) {
            const int row = idx >> 7;           /* 128 float4 per row */
            const int col = idx & 127;
            const int b   = row >> 13;          /* /NP */
            const int o   = row & (NP - 1);
            o4[((size_t)(b * ROWS_PER_B + o) << 7) + col] = x4[idx];
        }
        const int totp = NB * NP * 3;
        for (int idx = ct; idx < totp; idx += nth) {
            const int row = idx / 3, c = idx - row * 3;
            const int b = row >> 13, o = row & (NP - 1);
            outp[(size_t)(b * ROWS_PER_B + o) * 3 + c] = pos[idx];
        }
        return;
    }

    /* ------------------------- FPS path ---------------------------- */
    const int b    = blockIdx.x;
    const int tid  = threadIdx.x;
    const int lane = tid & 31;
    const int wid  = tid >> 5;

    extern __shared__ unsigned char smem_raw[];
    uint2*          wcand = reinterpret_cast<uint2*>(smem_raw + OFF_WCAND);
    int*            scnt  = reinterpret_cast<int*>(smem_raw + OFF_CNT);
    float*          sx    = reinterpret_cast<float*>(smem_raw + OFF_SX);
    float*          sy    = reinterpret_cast<float*>(smem_raw + OFF_SY);
    float*          sz    = reinterpret_cast<float*>(smem_raw + OFF_SZ);
    unsigned*       skey  = reinterpret_cast<unsigned*>(smem_raw + OFF_KEY);
    unsigned short* sid   = reinterpret_cast<unsigned short*>(smem_raw + OFF_SID);

    if (tid == 0) { scnt[0] = 0; scnt[1] = 0; }

    const float* pb = pos + (size_t)b * NP * 3;
    for (int i = tid; i < NP; i += TPB) {
        const float px = pb[3 * i + 0];
        const float py = pb[3 * i + 1];
        const float pz = pb[3 * i + 2];
        sx[i] = px; sy[i] = py; sz[i] = pz;
        skey[i] = expand10(quant10(px)) | (expand10(quant10(py)) << 1)
                | (expand10(quant10(pz)) << 2);
        sid[i]  = (unsigned short)i;
    }
    __syncthreads();

    /* bitonic sort (ascending key) of (u32 key, u16 payload) */
    for (int k = 2; k <= NP; k <<= 1) {
        for (int j = k >> 1; j > 0; j >>= 1) {
            for (int i = tid; i < NP; i += TPB) {
                const int ixj = i ^ j;
                if (ixj > i) {
                    const unsigned a = skey[i];
                    const unsigned c = skey[ixj];
                    const bool up = ((i & k) == 0);
                    if ((a > c) == up) {
                        skey[i] = c; skey[ixj] = a;
                        const unsigned short t = sid[i]; sid[i] = sid[ixj]; sid[ixj] = t;
                    }
                }
            }
            __syncthreads();
        }
    }

    /* ownership + permutation validity check (fallback = round 1) */
    int ids[8];
    int psum = 0, pxor = 0;
#pragma unroll
    for (int kk = 0; kk < 8; kk++) {
        ids[kk] = (int)sid[tid * 8 + kk];
        psum += ids[kk];
        pxor ^= ids[kk];
    }
    atomicAdd(&scnt[0], psum);
    atomicXor(&scnt[1], pxor);
    __syncthreads();
    const bool perm_ok = (scnt[0] == (NP * (NP - 1) / 2)) && (scnt[1] == 0);
    if (!perm_ok) {
#pragma unroll
        for (int kk = 0; kk < 8; kk++) ids[kk] = tid * 8 + kk;
    }

#define CSWP(a, bb) { if (ids[a] > ids[bb]) { int t = ids[a]; ids[a] = ids[bb]; ids[bb] = t; } }
    CSWP(0,1) CSWP(2,3) CSWP(4,5) CSWP(6,7)
    CSWP(0,2) CSWP(1,3) CSWP(4,6) CSWP(5,7)
    CSWP(1,2) CSWP(5,6)
    CSWP(0,4) CSWP(1,5) CSWP(2,6) CSWP(3,7)
    CSWP(1,4) CSWP(3,6)
    CSWP(2,4) CSWP(3,5)
    CSWP(3,4)
#undef CSWP

    /* owned points -> registers; lane bbox */
    unsigned long long px2[4], py2[4], pz2[4];
    float dist[8];
    float bxlo, bxhi, bylo, byhi, bzlo, bzhi;
    {
        float lx0 = sx[ids[0]], ly0 = sy[ids[0]], lz0 = sz[ids[0]];
        bxlo = bxhi = lx0; bylo = byhi = ly0; bzlo = bzhi = lz0;
        float lxp = lx0, lyp = ly0, lzp = lz0;
#pragma unroll
        for (int kk = 0; kk < 8; kk++) {
            const float lx = sx[ids[kk]], ly = sy[ids[kk]], lz = sz[ids[kk]];
            bxlo = fminf(bxlo, lx); bxhi = fmaxf(bxhi, lx);
            bylo = fminf(bylo, ly); byhi = fmaxf(byhi, ly);
            bzlo = fminf(bzlo, lz); bzhi = fmaxf(bzhi, lz);
            if (kk & 1) {
                px2[kk >> 1] = pack2(lxp, lx);
                py2[kk >> 1] = pack2(lyp, ly);
                pz2[kk >> 1] = pack2(lzp, lz);
            }
            lxp = lx; lyp = ly; lzp = lz;
            dist[kk] = 1e10f;
        }
    }

    /* warp-uniform AABB (one-time shfl reduction of lane boxes) */
    float wxlo = bxlo, wxhi = bxhi, wylo = bylo, wyhi = byhi, wzlo = bzlo, wzhi = bzhi;
#pragma unroll
    for (int off = 16; off > 0; off >>= 1) {
        wxlo = fminf(wxlo, __shfl_xor_sync(0xffffffffu, wxlo, off));
        wxhi = fmaxf(wxhi, __shfl_xor_sync(0xffffffffu, wxhi, off));
        wylo = fminf(wylo, __shfl_xor_sync(0xffffffffu, wylo, off));
        wyhi = fmaxf(wyhi, __shfl_xor_sync(0xffffffffu, wyhi, off));
        wzlo = fminf(wzlo, __shfl_xor_sync(0xffffffffu, wzlo, off));
        wzhi = fmaxf(wzhi, __shfl_xor_sync(0xffffffffu, wzhi, off));
    }

    float    tub  = 1e10f;
    int      tbid = ids[0];
    unsigned vm_u = __float_as_uint(1e10f);     /* cached warp candidate */
    unsigned im_u = (unsigned)ids[0];
    float    vm_f = 1e10f;

    int cur = 0;
    if (tid == 0) g_fps_idx[b * NS1] = 0;

    for (int s = 1; s < NS1; s++) {
        const float cx = sx[cur], cy = sy[cur], cz = sz[cur];     /* LDS bcast */

        /* tier 1: warp-uniform box test (exact-safe skip of whole warp) */
        const float wdx = cx - fminf(fmaxf(cx, wxlo), wxhi);
        const float wdy = cy - fminf(fmaxf(cy, wylo), wyhi);
        const float wdz = cz - fminf(fmaxf(cz, wzlo), wzhi);
        const float wdmin2 = wdx * wdx + wdy * wdy + wdz * wdz;

        if (wdmin2 * 0.99999f < vm_f) {
            /* tier 2: per-lane box test */
            const float ddx = cx - fminf(fmaxf(cx, bxlo), bxhi);
            const float ddy = cy - fminf(fmaxf(cy, bylo), byhi);
            const float ddz = cz - fminf(fmaxf(cz, bzlo), bzhi);
            const float dmin2 = ddx * ddx + ddy * ddy + ddz * ddz;
            const bool  upd   = (dmin2 * 0.99999f < tub);

            if (__any_sync(0xffffffffu, upd)) {
                if (upd) {
                    const unsigned long long ncx = pack2(-cx, -cx);
                    const unsigned long long ncy = pack2(-cy, -cy);
                    const unsigned long long ncz = pack2(-cz, -cz);
                    float best = -1.0f; int bi = ids[0];
#pragma unroll
                    for (int kk = 0; kk < 4; kk++) {
                        /* p + (-c) == p - c (RN); mul/add roundings == ref */
                        const unsigned long long dx = f32x2_add(px2[kk], ncx);
                        const unsigned long long dy = f32x2_add(py2[kk], ncy);
                        const unsigned long long dz = f32x2_add(pz2[kk], ncz);
                        const unsigned long long sm = f32x2_add(
                            f32x2_add(f32x2_mul(dx, dx), f32x2_mul(dy, dy)),
                            f32x2_mul(dz, dz));
                        float d0, d1;
                        unpack2(sm, d0, d1);
                        const float n0 = fminf(dist[2 * kk], d0);     dist[2 * kk] = n0;
                        if (n0 > best) { best = n0; bi = ids[2 * kk]; }
                        const float n1 = fminf(dist[2 * kk + 1], d1); dist[2 * kk + 1] = n1;
                        if (n1 > best) { best = n1; bi = ids[2 * kk + 1]; }
                    }
                    tub = best; tbid = bi;
                }
                /* warp argmax (convergent): (val desc, id asc) */
                const unsigned vb = __float_as_uint(tub);
                vm_u = __reduce_max_sync(0xffffffffu, vb);
                im_u = __reduce_min_sync(0xffffffffu,
                           (vb == vm_u) ? (unsigned)tbid : 0xFFFFFFFFu);
                vm_f = __uint_as_float(vm_u);
            }
        }
        /* clean warp (either tier): no lane's (tub,tbid) changed ->
           cached (vm_u, im_u) still the exact warp candidate          */

        const int sl = s & 1;
        if (lane == 0) wcand[(sl << 5) + wid] = make_uint2(vm_u, im_u);
        __syncthreads();

        /* every warp redundantly reduces the 32 warp candidates */
        const uint2 wc = wcand[(sl << 5) + lane];
        const unsigned vm2 = __reduce_max_sync(0xffffffffu, wc.x);
        const unsigned im2 = __reduce_min_sync(0xffffffffu,
                               (wc.x == vm2) ? wc.y : 0xFFFFFFFFu);
        cur = (int)im2;

        if (tid == 0) g_fps_idx[b * NS1 + s] = cur;
    }
}

/* ===================================================================
   Gather for SAMPLED rows only (scale 0.5 + 0.25); one 128-thread
   block per row. Scale 0.25 = first 2048 FPS indices (greedy prefix).
   =================================================================== */
__global__ void gather_kernel(const float* __restrict__ x,
                              const float* __restrict__ pos,
                              float* __restrict__ outx,
                              float* __restrict__ outp)
{
    const int r = blockIdx.x;                 /* 0 .. NB*(NS1+NS2)-1 */
    const int b = r / (NS1 + NS2);
    const int o = r - b * (NS1 + NS2);        /* 0 .. 6143           */

    const int src = (o < NS1) ? g_fps_idx[b * NS1 + o]
                              : g_fps_idx[b * NS1 + (o - NS1)];
    const int orow = b * ROWS_PER_B + NP + o;

    const size_t srow = (size_t)b * NP + (size_t)src;
    const float4* xin = reinterpret_cast<const float4*>(x + srow * ND);
    float4*       xo  = reinterpret_cast<float4*>(outx + (size_t)orow * ND);
    xo[threadIdx.x] = xin[threadIdx.x];

    if (threadIdx.x < 3)
        outp[(size_t)orow * 3 + threadIdx.x] = pos[srow * 3 + threadIdx.x];
}

extern "C" void kernel_launch(void* const* d_in, const int* in_sizes, int n_in,
                              void* d_out, int out_size)
{
    const float* x   = (const float*)d_in[0];   /* [B*P, D] f32 */
    const float* pos = (const float*)d_in[1];   /* [B*P, 3] f32 */

    float* outx = (float*)d_out;
    float* outp = outx + OUTX_ELEMS;

    cudaFuncSetAttribute(fps_kernel, cudaFuncAttributeMaxDynamicSharedMemorySize,
                         SMEM_TOTAL);

    fps_kernel<<<NB + NCOPY, TPB, SMEM_TOTAL>>>(pos, x, outx, outp);
    gather_kernel<<<NB * (NS1 + NS2), 128>>>(x, pos, outx, outp);
}

// round 6
// speedup vs baseline: 1.3001x; 1.3001x over previous
#include <cuda_runtime.h>
#include <cstdint>

#define NB 4
#define NP 8192
#define ND 512
#define NS1 4096
#define NS2 2048
#define ROWS_PER_B (NP + NS1 + NS2)   /* 14336 */
#define OUTX_ELEMS ((size_t)NB * ROWS_PER_B * ND)
#define TPB 1024
#define NCOPY 144                      /* copy CTAs fused into fps launch */

/* smem layout (bytes) */
#define OFF_WCAND 0        /* uint2[64]  = 512           */
#define OFF_CNT   512      /* int ssum, int sxor         */
#define OFF_SX    1024
#define OFF_SY    (OFF_SX + NP * 4)
#define OFF_SZ    (OFF_SY + NP * 4)
#define OFF_KEY   (OFF_SZ + NP * 4)          /* u32[8192] */
#define OFF_SID   (OFF_KEY + NP * 4)         /* u16[8192] */
#define SMEM_TOTAL (OFF_SID + NP * 2)        /* 148480 B  */

__device__ int g_fps_idx[NB * NS1];

/* ---------------- packed f32x2 helpers (proven) -------------------- */
__device__ __forceinline__ unsigned long long f32x2_add(unsigned long long a, unsigned long long b) {
    unsigned long long r;
    asm("add.rn.f32x2 %0, %1, %2;" : "=l"(r) : "l"(a), "l"(b));
    return r;
}
__device__ __forceinline__ unsigned long long f32x2_mul(unsigned long long a, unsigned long long b) {
    unsigned long long r;
    asm("mul.rn.f32x2 %0, %1, %2;" : "=l"(r) : "l"(a), "l"(b));
    return r;
}
__device__ __forceinline__ unsigned long long pack2(float lo, float hi) {
    unsigned long long r;
    asm("mov.b64 %0, {%1, %2};" : "=l"(r) : "f"(lo), "f"(hi));
    return r;
}
__device__ __forceinline__ void unpack2(unsigned long long v, float& lo, float& hi) {
    asm("mov.b64 {%0, %1}, %2;" : "=f"(lo), "=f"(hi) : "l"(v));
}

/* ---------------- Morton helpers ----------------------------------- */
__device__ __forceinline__ unsigned expand10(unsigned v) {
    v &= 0x3FFu;
    v = (v | (v << 16)) & 0x030000FFu;
    v = (v | (v <<  8)) & 0x0300F00Fu;
    v = (v | (v <<  4)) & 0x030C30C3u;
    v = (v | (v <<  2)) & 0x09249249u;
    return v;
}
__device__ __forceinline__ unsigned quant10(float x) {
    float q = (x + 8.0f) * 64.0f;
    q = fminf(fmaxf(q, 0.0f), 1023.0f);
    return (unsigned)q;
}

/* ===================================================================
   Fused kernel.
   blockIdx < NB  : FPS for batch blockIdx — EXACT round-4 hot loop
                    (lane-level 8-pt AABB prune, cached warp candidate,
                    one barrier per step). No warp-uniform pre-test:
                    proven pure issue overhead at 8 warps/SMSP.
   blockIdx >= NB : static-copy CTAs — stream the scale-1.0 rows
                    (FPS-independent) on the otherwise idle SMs.
   =================================================================== */
__global__ void __launch_bounds__(TPB, 1) fps_kernel(const float* __restrict__ pos,
                                                     const float* __restrict__ x,
                                                     float* __restrict__ outx,
                                                     float* __restrict__ outp)
{
    /* ------------------- static copy path -------------------------- */
    if (blockIdx.x >= NB) {
        const int  ct  = (int)(blockIdx.x - NB) * TPB + threadIdx.x;
        const int  nth = NCOPY * TPB;
        const float4* x4 = reinterpret_cast<const float4*>(x);
        float4*       o4 = reinterpret_cast<float4*>(outx);
        const int totf4 = NB * NP * (ND / 4);
        for (int idx = ct; idx < totf4; idx += nth) {
            const int row = idx >> 7;
            const int col = idx & 127;
            const int b   = row >> 13;
            const int o   = row & (NP - 1);
            o4[((size_t)(b * ROWS_PER_B + o) << 7) + col] = x4[idx];
        }
        const int totp = NB * NP * 3;
        for (int idx = ct; idx < totp; idx += nth) {
            const int row = idx / 3, c = idx - row * 3;
            const int b = row >> 13, o = row & (NP - 1);
            outp[(size_t)(b * ROWS_PER_B + o) * 3 + c] = pos[idx];
        }
        return;
    }

    /* ------------------------- FPS path ---------------------------- */
    const int b    = blockIdx.x;
    const int tid  = threadIdx.x;
    const int lane = tid & 31;
    const int wid  = tid >> 5;

    extern __shared__ unsigned char smem_raw[];
    uint2*          wcand = reinterpret_cast<uint2*>(smem_raw + OFF_WCAND);
    int*            scnt  = reinterpret_cast<int*>(smem_raw + OFF_CNT);
    float*          sx    = reinterpret_cast<float*>(smem_raw + OFF_SX);
    float*          sy    = reinterpret_cast<float*>(smem_raw + OFF_SY);
    float*          sz    = reinterpret_cast<float*>(smem_raw + OFF_SZ);
    unsigned*       skey  = reinterpret_cast<unsigned*>(smem_raw + OFF_KEY);
    unsigned short* sid   = reinterpret_cast<unsigned short*>(smem_raw + OFF_SID);

    if (tid == 0) { scnt[0] = 0; scnt[1] = 0; }

    const float* pb = pos + (size_t)b * NP * 3;
    for (int i = tid; i < NP; i += TPB) {
        const float px = pb[3 * i + 0];
        const float py = pb[3 * i + 1];
        const float pz = pb[3 * i + 2];
        sx[i] = px; sy[i] = py; sz[i] = pz;
        skey[i] = expand10(quant10(px)) | (expand10(quant10(py)) << 1)
                | (expand10(quant10(pz)) << 2);
        sid[i]  = (unsigned short)i;
    }
    __syncthreads();

    /* bitonic sort (ascending key) of (u32 key, u16 payload) */
    for (int k = 2; k <= NP; k <<= 1) {
        for (int j = k >> 1; j > 0; j >>= 1) {
            for (int i = tid; i < NP; i += TPB) {
                const int ixj = i ^ j;
                if (ixj > i) {
                    const unsigned a = skey[i];
                    const unsigned c = skey[ixj];
                    const bool up = ((i & k) == 0);
                    if ((a > c) == up) {
                        skey[i] = c; skey[ixj] = a;
                        const unsigned short t = sid[i]; sid[i] = sid[ixj]; sid[ixj] = t;
                    }
                }
            }
            __syncthreads();
        }
    }

    /* ownership + permutation validity check (fallback = round 1) */
    int ids[8];
    int psum = 0, pxor = 0;
#pragma unroll
    for (int kk = 0; kk < 8; kk++) {
        ids[kk] = (int)sid[tid * 8 + kk];
        psum += ids[kk];
        pxor ^= ids[kk];
    }
    atomicAdd(&scnt[0], psum);
    atomicXor(&scnt[1], pxor);
    __syncthreads();
    const bool perm_ok = (scnt[0] == (NP * (NP - 1) / 2)) && (scnt[1] == 0);
    if (!perm_ok) {
#pragma unroll
        for (int kk = 0; kk < 8; kk++) ids[kk] = tid * 8 + kk;
    }

#define CSWP(a, bb) { if (ids[a] > ids[bb]) { int t = ids[a]; ids[a] = ids[bb]; ids[bb] = t; } }
    CSWP(0,1) CSWP(2,3) CSWP(4,5) CSWP(6,7)
    CSWP(0,2) CSWP(1,3) CSWP(4,6) CSWP(5,7)
    CSWP(1,2) CSWP(5,6)
    CSWP(0,4) CSWP(1,5) CSWP(2,6) CSWP(3,7)
    CSWP(1,4) CSWP(3,6)
    CSWP(2,4) CSWP(3,5)
    CSWP(3,4)
#undef CSWP

    /* owned points -> registers; lane bbox */
    unsigned long long px2[4], py2[4], pz2[4];
    float dist[8];
    float bxlo, bxhi, bylo, byhi, bzlo, bzhi;
    {
        float lx0 = sx[ids[0]], ly0 = sy[ids[0]], lz0 = sz[ids[0]];
        bxlo = bxhi = lx0; bylo = byhi = ly0; bzlo = bzhi = lz0;
        float lxp = lx0, lyp = ly0, lzp = lz0;
#pragma unroll
        for (int kk = 0; kk < 8; kk++) {
            const float lx = sx[ids[kk]], ly = sy[ids[kk]], lz = sz[ids[kk]];
            bxlo = fminf(bxlo, lx); bxhi = fmaxf(bxhi, lx);
            bylo = fminf(bylo, ly); byhi = fmaxf(byhi, ly);
            bzlo = fminf(bzlo, lz); bzhi = fmaxf(bzhi, lz);
            if (kk & 1) {
                px2[kk >> 1] = pack2(lxp, lx);
                py2[kk >> 1] = pack2(lyp, ly);
                pz2[kk >> 1] = pack2(lzp, lz);
            }
            lxp = lx; lyp = ly; lzp = lz;
            dist[kk] = 1e10f;
        }
    }

    float tub  = 1e10f;    /* exact max of this thread's dists          */
    int   tbid = ids[0];   /* first original index achieving that max   */

    int cur = 0;
    if (tid == 0) g_fps_idx[b * NS1] = 0;

    for (int s = 1; s < NS1; s++) {
        const float cx = sx[cur], cy = sy[cur], cz = sz[cur];    /* LDS bcast */

        /* exact-safe skip test: lower-bound distance from c to lane bbox */
        const float ddx = cx - fminf(fmaxf(cx, bxlo), bxhi);
        const float ddy = cy - fminf(fmaxf(cy, bylo), byhi);
        const float ddz = cz - fminf(fmaxf(cz, bzlo), bzhi);
        const float dmin2 = ddx * ddx + ddy * ddy + ddz * ddz;
        const bool  skip  = (dmin2 * 0.99999f >= tub);

        if (__any_sync(0xffffffffu, !skip)) {
            const unsigned long long ncx = pack2(-cx, -cx);
            const unsigned long long ncy = pack2(-cy, -cy);
            const unsigned long long ncz = pack2(-cz, -cz);
            float best = -1.0f; int bi = ids[0];
#pragma unroll
            for (int kk = 0; kk < 4; kk++) {
                /* p + (-c) == p - c (RN); separate mul/add roundings == ref */
                const unsigned long long dx = f32x2_add(px2[kk], ncx);
                const unsigned long long dy = f32x2_add(py2[kk], ncy);
                const unsigned long long dz = f32x2_add(pz2[kk], ncz);
                const unsigned long long sm = f32x2_add(
                    f32x2_add(f32x2_mul(dx, dx), f32x2_mul(dy, dy)), f32x2_mul(dz, dz));
                float d0, d1;
                unpack2(sm, d0, d1);
                const float n0 = fminf(dist[2 * kk], d0);     dist[2 * kk] = n0;
                if (n0 > best) { best = n0; bi = ids[2 * kk]; }      /* strict > */
                const float n1 = fminf(dist[2 * kk + 1], d1); dist[2 * kk + 1] = n1;
                if (n1 > best) { best = n1; bi = ids[2 * kk + 1]; }
            }
            tub = best; tbid = bi;
        }
        /* skip-step: dists provably unchanged -> (tub, tbid) still exact */

        /* warp argmax every step: (val desc, id asc) */
        const unsigned vb = __float_as_uint(tub);                 /* dist >= 0 */
        const unsigned vm = __reduce_max_sync(0xffffffffu, vb);
        const unsigned im = __reduce_min_sync(0xffffffffu,
                              (vb == vm) ? (unsigned)tbid : 0xFFFFFFFFu);
        const int sl = s & 1;
        if (lane == 0) wcand[(sl << 5) + wid] = make_uint2(vm, im);
        __syncthreads();

        /* every warp redundantly reduces the 32 warp candidates */
        const uint2 wc = wcand[(sl << 5) + lane];
        const unsigned vm2 = __reduce_max_sync(0xffffffffu, wc.x);
        const unsigned im2 = __reduce_min_sync(0xffffffffu,
                               (wc.x == vm2) ? wc.y : 0xFFFFFFFFu);
        cur = (int)im2;

        if (tid == 0) g_fps_idx[b * NS1 + s] = cur;
    }
}

/* ===================================================================
   Gather for SAMPLED rows only (scale 0.5 + 0.25); one 128-thread
   block per row. Scale 0.25 = first 2048 FPS indices (greedy prefix).
   =================================================================== */
__global__ void gather_kernel(const float* __restrict__ x,
                              const float* __restrict__ pos,
                              float* __restrict__ outx,
                              float* __restrict__ outp)
{
    const int r = blockIdx.x;                 /* 0 .. NB*(NS1+NS2)-1 */
    const int b = r / (NS1 + NS2);
    const int o = r - b * (NS1 + NS2);        /* 0 .. 6143           */

    const int src = (o < NS1) ? g_fps_idx[b * NS1 + o]
                              : g_fps_idx[b * NS1 + (o - NS1)];
    const int orow = b * ROWS_PER_B + NP + o;

    const size_t srow = (size_t)b * NP + (size_t)src;
    const float4* xin = reinterpret_cast<const float4*>(x + srow * ND);
    float4*       xo  = reinterpret_cast<float4*>(outx + (size_t)orow * ND);
    xo[threadIdx.x] = xin[threadIdx.x];

    if (threadIdx.x < 3)
        outp[(size_t)orow * 3 + threadIdx.x] = pos[srow * 3 + threadIdx.x];
}

extern "C" void kernel_launch(void* const* d_in, const int* in_sizes, int n_in,
                              void* d_out, int out_size)
{
    const float* x   = (const float*)d_in[0];   /* [B*P, D] f32 */
    const float* pos = (const float*)d_in[1];   /* [B*P, 3] f32 */

    float* outx = (float*)d_out;
    float* outp = outx + OUTX_ELEMS;

    cudaFuncSetAttribute(fps_kernel, cudaFuncAttributeMaxDynamicSharedMemorySize,
                         SMEM_TOTAL);

    fps_kernel<<<NB + NCOPY, TPB, SMEM_TOTAL>>>(pos, x, outx, outp);
    gather_kernel<<<NB * (NS1 + NS2), 128>>>(x, pos, outx, outp);
}

// round 7
// speedup vs baseline: 1.3110x; 1.0083x over previous
#include <cuda_runtime.h>
#include <cstdint>

#define NB 4
#define NP 8192
#define ND 512
#define NS1 4096
#define NS2 2048
#define ROWS_PER_B (NP + NS1 + NS2)   /* 14336 */
#define OUTX_ELEMS ((size_t)NB * ROWS_PER_B * ND)
#define TPB 512                        /* 16 warps -> 4 per SMSP       */
#define PPT 16                         /* points per thread            */
#define NCOPY 144                      /* copy CTAs fused into fps     */

/* smem layout (bytes) */
#define OFF_WCAND 0        /* uint2[64]  = 512           */
#define OFF_CNT   512      /* int ssum, int sxor         */
#define OFF_SX    1024
#define OFF_SY    (OFF_SX + NP * 4)
#define OFF_SZ    (OFF_SY + NP * 4)
#define OFF_KEY   (OFF_SZ + NP * 4)          /* u32[8192] */
#define OFF_SID   (OFF_KEY + NP * 4)         /* u16[8192] */
#define SMEM_TOTAL (OFF_SID + NP * 2)        /* 148480 B  */

__device__ int g_fps_idx[NB * NS1];

/* ---------------- packed f32x2 helpers (proven) -------------------- */
__device__ __forceinline__ unsigned long long f32x2_add(unsigned long long a, unsigned long long b) {
    unsigned long long r;
    asm("add.rn.f32x2 %0, %1, %2;" : "=l"(r) : "l"(a), "l"(b));
    return r;
}
__device__ __forceinline__ unsigned long long f32x2_mul(unsigned long long a, unsigned long long b) {
    unsigned long long r;
    asm("mul.rn.f32x2 %0, %1, %2;" : "=l"(r) : "l"(a), "l"(b));
    return r;
}
__device__ __forceinline__ unsigned long long pack2(float lo, float hi) {
    unsigned long long r;
    asm("mov.b64 %0, {%1, %2};" : "=l"(r) : "f"(lo), "f"(hi));
    return r;
}
__device__ __forceinline__ void unpack2(unsigned long long v, float& lo, float& hi) {
    asm("mov.b64 {%0, %1}, %2;" : "=f"(lo), "=f"(hi) : "l"(v));
}

/* ---------------- Morton helpers ----------------------------------- */
__device__ __forceinline__ unsigned expand10(unsigned v) {
    v &= 0x3FFu;
    v = (v | (v << 16)) & 0x030000FFu;
    v = (v | (v <<  8)) & 0x0300F00Fu;
    v = (v | (v <<  4)) & 0x030C30C3u;
    v = (v | (v <<  2)) & 0x09249249u;
    return v;
}
__device__ __forceinline__ unsigned quant10(float x) {
    float q = (x + 8.0f) * 64.0f;
    q = fminf(fmaxf(q, 0.0f), 1023.0f);
    return (unsigned)q;
}

/* ===================================================================
   Fused kernel.
   blockIdx < NB  : FPS for batch blockIdx — round-6 algorithm at
                    512 threads / 16 pts per thread (halves the fixed
                    per-step issue cost at 4 warps/SMSP).
   blockIdx >= NB : static-copy CTAs — stream the scale-1.0 rows
                    (FPS-independent) on the otherwise idle SMs.
   =================================================================== */
__global__ void __launch_bounds__(TPB, 1) fps_kernel(const float* __restrict__ pos,
                                                     const float* __restrict__ x,
                                                     float* __restrict__ outx,
                                                     float* __restrict__ outp)
{
    /* ------------------- static copy path -------------------------- */
    if (blockIdx.x >= NB) {
        const int  ct  = (int)(blockIdx.x - NB) * TPB + threadIdx.x;
        const int  nth = NCOPY * TPB;
        const float4* x4 = reinterpret_cast<const float4*>(x);
        float4*       o4 = reinterpret_cast<float4*>(outx);
        const int totf4 = NB * NP * (ND / 4);
        for (int idx = ct; idx < totf4; idx += nth) {
            const int row = idx >> 7;
            const int col = idx & 127;
            const int b   = row >> 13;
            const int o   = row & (NP - 1);
            o4[((size_t)(b * ROWS_PER_B + o) << 7) + col] = x4[idx];
        }
        const int totp = NB * NP * 3;
        for (int idx = ct; idx < totp; idx += nth) {
            const int row = idx / 3, c = idx - row * 3;
            const int b = row >> 13, o = row & (NP - 1);
            outp[(size_t)(b * ROWS_PER_B + o) * 3 + c] = pos[idx];
        }
        return;
    }

    /* ------------------------- FPS path ---------------------------- */
    const int b    = blockIdx.x;
    const int tid  = threadIdx.x;
    const int lane = tid & 31;
    const int wid  = tid >> 5;

    extern __shared__ unsigned char smem_raw[];
    uint2*          wcand = reinterpret_cast<uint2*>(smem_raw + OFF_WCAND);
    int*            scnt  = reinterpret_cast<int*>(smem_raw + OFF_CNT);
    float*          sx    = reinterpret_cast<float*>(smem_raw + OFF_SX);
    float*          sy    = reinterpret_cast<float*>(smem_raw + OFF_SY);
    float*          sz    = reinterpret_cast<float*>(smem_raw + OFF_SZ);
    unsigned*       skey  = reinterpret_cast<unsigned*>(smem_raw + OFF_KEY);
    unsigned short* sid   = reinterpret_cast<unsigned short*>(smem_raw + OFF_SID);

    if (tid == 0) { scnt[0] = 0; scnt[1] = 0; }

    const float* pb = pos + (size_t)b * NP * 3;
    for (int i = tid; i < NP; i += TPB) {
        const float px = pb[3 * i + 0];
        const float py = pb[3 * i + 1];
        const float pz = pb[3 * i + 2];
        sx[i] = px; sy[i] = py; sz[i] = pz;
        skey[i] = expand10(quant10(px)) | (expand10(quant10(py)) << 1)
                | (expand10(quant10(pz)) << 2);
        sid[i]  = (unsigned short)i;
    }
    __syncthreads();

    /* bitonic sort (ascending key) of (u32 key, u16 payload) */
    for (int k = 2; k <= NP; k <<= 1) {
        for (int j = k >> 1; j > 0; j >>= 1) {
            for (int i = tid; i < NP; i += TPB) {
                const int ixj = i ^ j;
                if (ixj > i) {
                    const unsigned a = skey[i];
                    const unsigned c = skey[ixj];
                    const bool up = ((i & k) == 0);
                    if ((a > c) == up) {
                        skey[i] = c; skey[ixj] = a;
                        const unsigned short t = sid[i]; sid[i] = sid[ixj]; sid[ixj] = t;
                    }
                }
            }
            __syncthreads();
        }
    }

    /* ownership + permutation validity check (fallback = identity) */
    int ids[PPT];
    int psum = 0, pxor = 0;
#pragma unroll
    for (int kk = 0; kk < PPT; kk++) {
        ids[kk] = (int)sid[tid * PPT + kk];
        psum += ids[kk];
        pxor ^= ids[kk];
    }
    atomicAdd(&scnt[0], psum);
    atomicXor(&scnt[1], pxor);
    __syncthreads();
    const bool perm_ok = (scnt[0] == (NP * (NP - 1) / 2)) && (scnt[1] == 0);
    if (!perm_ok) {
#pragma unroll
        for (int kk = 0; kk < PPT; kk++) ids[kk] = tid * PPT + kk;
    }

    /* 16-element Batcher odd-even mergesort network (63 comparators):
       ids ascending -> strict '>' scan keeps first (lowest) index      */
#define CSWP(a, bb) { if (ids[a] > ids[bb]) { int t = ids[a]; ids[a] = ids[bb]; ids[bb] = t; } }
    /* p=1 */
    CSWP(0,1) CSWP(2,3) CSWP(4,5) CSWP(6,7) CSWP(8,9) CSWP(10,11) CSWP(12,13) CSWP(14,15)
    /* p=2, k=2 */
    CSWP(0,2) CSWP(1,3) CSWP(4,6) CSWP(5,7) CSWP(8,10) CSWP(9,11) CSWP(12,14) CSWP(13,15)
    /* p=2, k=1 */
    CSWP(1,2) CSWP(5,6) CSWP(9,10) CSWP(13,14)
    /* p=4, k=4 */
    CSWP(0,4) CSWP(1,5) CSWP(2,6) CSWP(3,7) CSWP(8,12) CSWP(9,13) CSWP(10,14) CSWP(11,15)
    /* p=4, k=2 */
    CSWP(2,4) CSWP(3,5) CSWP(10,12) CSWP(11,13)
    /* p=4, k=1 */
    CSWP(1,2) CSWP(3,4) CSWP(5,6) CSWP(9,10) CSWP(11,12) CSWP(13,14)
    /* p=8, k=8 */
    CSWP(0,8) CSWP(1,9) CSWP(2,10) CSWP(3,11) CSWP(4,12) CSWP(5,13) CSWP(6,14) CSWP(7,15)
    /* p=8, k=4 */
    CSWP(4,8) CSWP(5,9) CSWP(6,10) CSWP(7,11)
    /* p=8, k=2 */
    CSWP(2,4) CSWP(3,5) CSWP(6,8) CSWP(7,9) CSWP(10,12) CSWP(11,13)
    /* p=8, k=1 */
    CSWP(1,2) CSWP(3,4) CSWP(5,6) CSWP(7,8) CSWP(9,10) CSWP(11,12) CSWP(13,14)
#undef CSWP

    /* owned points -> registers; lane bbox over 16 pts */
    unsigned long long px2[PPT / 2], py2[PPT / 2], pz2[PPT / 2];
    float dist[PPT];
    float bxlo, bxhi, bylo, byhi, bzlo, bzhi;
    {
        float lx0 = sx[ids[0]], ly0 = sy[ids[0]], lz0 = sz[ids[0]];
        bxlo = bxhi = lx0; bylo = byhi = ly0; bzlo = bzhi = lz0;
        float lxp = lx0, lyp = ly0, lzp = lz0;
#pragma unroll
        for (int kk = 0; kk < PPT; kk++) {
            const float lx = sx[ids[kk]], ly = sy[ids[kk]], lz = sz[ids[kk]];
            bxlo = fminf(bxlo, lx); bxhi = fmaxf(bxhi, lx);
            bylo = fminf(bylo, ly); byhi = fmaxf(byhi, ly);
            bzlo = fminf(bzlo, lz); bzhi = fmaxf(bzhi, lz);
            if (kk & 1) {
                px2[kk >> 1] = pack2(lxp, lx);
                py2[kk >> 1] = pack2(lyp, ly);
                pz2[kk >> 1] = pack2(lzp, lz);
            }
            lxp = lx; lyp = ly; lzp = lz;
            dist[kk] = 1e10f;
        }
    }

    float tub  = 1e10f;    /* exact max of this thread's dists          */
    int   tbid = ids[0];   /* first original index achieving that max   */

    int cur = 0;
    if (tid == 0) g_fps_idx[b * NS1] = 0;

    for (int s = 1; s < NS1; s++) {
        const float cx = sx[cur], cy = sy[cur], cz = sz[cur];    /* LDS bcast */

        /* exact-safe skip test: lower-bound distance from c to lane bbox */
        const float ddx = cx - fminf(fmaxf(cx, bxlo), bxhi);
        const float ddy = cy - fminf(fmaxf(cy, bylo), byhi);
        const float ddz = cz - fminf(fmaxf(cz, bzlo), bzhi);
        const float dmin2 = ddx * ddx + ddy * ddy + ddz * ddz;
        const bool  skip  = (dmin2 * 0.99999f >= tub);

        if (__any_sync(0xffffffffu, !skip)) {
            const unsigned long long ncx = pack2(-cx, -cx);
            const unsigned long long ncy = pack2(-cy, -cy);
            const unsigned long long ncz = pack2(-cz, -cz);
            float best = -1.0f; int bi = ids[0];
#pragma unroll
            for (int kk = 0; kk < PPT / 2; kk++) {
                /* p + (-c) == p - c (RN); separate mul/add roundings == ref */
                const unsigned long long dx = f32x2_add(px2[kk], ncx);
                const unsigned long long dy = f32x2_add(py2[kk], ncy);
                const unsigned long long dz = f32x2_add(pz2[kk], ncz);
                const unsigned long long sm = f32x2_add(
                    f32x2_add(f32x2_mul(dx, dx), f32x2_mul(dy, dy)), f32x2_mul(dz, dz));
                float d0, d1;
                unpack2(sm, d0, d1);
                const float n0 = fminf(dist[2 * kk], d0);     dist[2 * kk] = n0;
                if (n0 > best) { best = n0; bi = ids[2 * kk]; }      /* strict > */
                const float n1 = fminf(dist[2 * kk + 1], d1); dist[2 * kk + 1] = n1;
                if (n1 > best) { best = n1; bi = ids[2 * kk + 1]; }
            }
            tub = best; tbid = bi;
        }
        /* skip-step: dists provably unchanged -> (tub, tbid) still exact */

        /* warp argmax every step: (val desc, id asc) */
        const unsigned vb = __float_as_uint(tub);                 /* dist >= 0 */
        const unsigned vm = __reduce_max_sync(0xffffffffu, vb);
        const unsigned im = __reduce_min_sync(0xffffffffu,
                              (vb == vm) ? (unsigned)tbid : 0xFFFFFFFFu);
        const int sl = s & 1;
        if (lane == 0) wcand[(sl << 4) + wid] = make_uint2(vm, im);
        __syncthreads();

        /* every warp redundantly reduces the 16 warp candidates */
        const uint2 wc = (lane < 16) ? wcand[(sl << 4) + lane] : make_uint2(0u, 0u);
        const unsigned vm2 = __reduce_max_sync(0xffffffffu, wc.x);
        const unsigned im2 = __reduce_min_sync(0xffffffffu,
                               (wc.x == vm2) ? wc.y : 0xFFFFFFFFu);
        cur = (int)im2;

        if (tid == 0) g_fps_idx[b * NS1 + s] = cur;
    }
}

/* ===================================================================
   Gather for SAMPLED rows only (scale 0.5 + 0.25); one 128-thread
   block per row. Scale 0.25 = first 2048 FPS indices (greedy prefix).
   =================================================================== */
__global__ void gather_kernel(const float* __restrict__ x,
                              const float* __restrict__ pos,
                              float* __restrict__ outx,
                              float* __restrict__ outp)
{
    const int r = blockIdx.x;                 /* 0 .. NB*(NS1+NS2)-1 */
    const int b = r / (NS1 + NS2);
    const int o = r - b * (NS1 + NS2);        /* 0 .. 6143           */

    const int src = (o < NS1) ? g_fps_idx[b * NS1 + o]
                              : g_fps_idx[b * NS1 + (o - NS1)];
    const int orow = b * ROWS_PER_B + NP + o;

    const size_t srow = (size_t)b * NP + (size_t)src;
    const float4* xin = reinterpret_cast<const float4*>(x + srow * ND);
    float4*       xo  = reinterpret_cast<float4*>(outx + (size_t)orow * ND);
    xo[threadIdx.x] = xin[threadIdx.x];

    if (threadIdx.x < 3)
        outp[(size_t)orow * 3 + threadIdx.x] = pos[srow * 3 + threadIdx.x];
}

extern "C" void kernel_launch(void* const* d_in, const int* in_sizes, int n_in,
                              void* d_out, int out_size)
{
    const float* x   = (const float*)d_in[0];   /* [B*P, D] f32 */
    const float* pos = (const float*)d_in[1];   /* [B*P, 3] f32 */

    float* outx = (float*)d_out;
    float* outp = outx + OUTX_ELEMS;

    cudaFuncSetAttribute(fps_kernel, cudaFuncAttributeMaxDynamicSharedMemorySize,
                         SMEM_TOTAL);

    fps_kernel<<<NB + NCOPY, TPB, SMEM_TOTAL>>>(pos, x, outx, outp);
    gather_kernel<<<NB * (NS1 + NS2), 128>>>(x, pos, outx, outp);
}